// round 2
// baseline (speedup 1.0000x reference)
#include <cuda_runtime.h>
#include <float.h>
#include <math.h>

// Problem constants
#define Bn   4
#define Qn   4
#define Fn   20
#define OBJn 20
#define Dn   4096
#define Mn   1000
#define ROWn (OBJn * Dn)          // 81920 floats per (frame|mem) row
#define BFn  (Bn * Fn)            // 80
#define KSPLIT 16
#define KPER   (Dn / KSPLIT)      // 256
#define MPAD 2048

static const size_t RPN = (size_t)Qn * Bn * Fn * ROWn;   // 26,214,400 elems per big output

// ---------------- device scratch (static allocation; no cudaMalloc allowed) ----------
__device__ float g_rmaxn[BFn * Dn];              // 1.3 MB: normalized maxpooled R rows
__device__ float g_invnorm[BFn * OBJn];          // per-region inverse norms
__device__ float g_partial[KSPLIT * BFn * MPAD]; // 10.5 MB: GEMM k-split partial sums (raw dots)
__device__ float g_psq[KSPLIT * MPAD];           // k-split partial sumsq of maxpooled mem rows
__device__ int   g_sim[2 * BFn];                 // sim1 (0..79), sim2 (80..159)
__device__ int   g_high[16], g_low[16], g_rowP[16], g_rowN[16];

// ---------------- helpers ----------------
__device__ __forceinline__ float block_reduce_sum(float v) {
    __shared__ float sh[32];
    __shared__ float res;
    int lane = threadIdx.x & 31, w = threadIdx.x >> 5;
#pragma unroll
    for (int o = 16; o; o >>= 1) v += __shfl_down_sync(0xffffffffu, v, o);
    __syncthreads();                 // protect sh/res reuse across calls
    if (!lane) sh[w] = v;
    __syncthreads();
    if (w == 0) {
        float x = (lane < (int)(blockDim.x >> 5)) ? sh[lane] : 0.f;
#pragma unroll
        for (int o = 16; o; o >>= 1) x += __shfl_down_sync(0xffffffffu, x, o);
        if (!lane) res = x;
    }
    __syncthreads();
    return res;
}

__device__ __forceinline__ float4 fmax4(float4 a, float4 b) {
    a.x = fmaxf(a.x, b.x); a.y = fmaxf(a.y, b.y);
    a.z = fmaxf(a.z, b.z); a.w = fmaxf(a.w, b.w);
    return a;
}

// ---------------- K2: per-(b,f) region norms + maxpool + l2norm -> g_rmaxn, g_invnorm --
__global__ __launch_bounds__(256) void k_rstats(const float* __restrict__ inp) {
    int bf = blockIdx.x;
    const float* base = inp + (size_t)bf * ROWn;
    float4 mx[4];
#pragma unroll
    for (int i = 0; i < 4; i++) mx[i] = make_float4(-FLT_MAX, -FLT_MAX, -FLT_MAX, -FLT_MAX);
    for (int o = 0; o < OBJn; o++) {
        float4 x[4];
        const float4* p = (const float4*)(base + (size_t)o * Dn);
        float s = 0.f;
#pragma unroll
        for (int i = 0; i < 4; i++) {
            x[i] = p[threadIdx.x + i * 256];
            s += x[i].x * x[i].x + x[i].y * x[i].y + x[i].z * x[i].z + x[i].w * x[i].w;
        }
        s = block_reduce_sum(s);
        float inv = 1.f / fmaxf(sqrtf(s), 1e-12f);
        if (threadIdx.x == 0) g_invnorm[bf * OBJn + o] = inv;
#pragma unroll
        for (int i = 0; i < 4; i++) {
            float4 v = x[i];
            v.x *= inv; v.y *= inv; v.z *= inv; v.w *= inv;
            mx[i] = fmax4(mx[i], v);
        }
    }
    float s2 = 0.f;
#pragma unroll
    for (int i = 0; i < 4; i++)
        s2 += mx[i].x * mx[i].x + mx[i].y * mx[i].y + mx[i].z * mx[i].z + mx[i].w * mx[i].w;
    s2 = block_reduce_sum(s2);
    float inv2 = 1.f / fmaxf(sqrtf(s2), 1e-12f);
    float4* out = (float4*)(g_rmaxn + (size_t)bf * Dn);
#pragma unroll
    for (int i = 0; i < 4; i++) {
        float4 v = mx[i];
        v.x *= inv2; v.y *= inv2; v.z *= inv2; v.w *= inv2;
        out[threadIdx.x + i * 256] = v;
    }
}

// ---------------- K3: FUSED maxpool + GEMM ----------------
// scores_raw = Rmaxn[80,4096] @ maxpool(mem)[4096,2000]; also per-row sumsq partials.
// grid (32 m-tiles of 64, 16 k-splits of 256), 256 threads.
// Each raw mem byte is read exactly once chip-wide (m-tiles x k-splits partition it).
__global__ __launch_bounds__(256) void k_gemm_fused(const float* __restrict__ mem1,
                                                    const float* __restrict__ mem2) {
    __shared__ float As[80][33];
    __shared__ float Bs[64][33];
    int tid = threadIdx.x;
    int m0 = blockIdx.x * 64;
    int ks = blockIdx.y;
    int kbase = ks * KPER;

    // B-load mapping: thread owns (row lm, 4-float group kq) and (row lm+32, kq)
    int lm = tid >> 3;            // 0..31
    int kq = tid & 7;             // 0..7  (8*4 = 32 k per chunk)
    int mgA = m0 + lm, mgB = m0 + lm + 32;
    bool vA = (mgA < 2 * Mn), vB = (mgB < 2 * Mn);
    const float* rpA = vA ? ((mgA < Mn) ? mem1 + (size_t)mgA * ROWn
                                        : mem2 + (size_t)(mgA - Mn) * ROWn) : mem1;
    const float* rpB = vB ? ((mgB < Mn) ? mem1 + (size_t)mgB * ROWn
                                        : mem2 + (size_t)(mgB - Mn) * ROWn) : mem1;
    const float4* pA4 = (const float4*)rpA;
    const float4* pB4 = (const float4*)rpB;

    // compute mapping: 5x4 micro-tile
    int tx = tid & 15, ty = tid >> 4;
    float acc[5][4];
#pragma unroll
    for (int i = 0; i < 5; i++)
#pragma unroll
        for (int j = 0; j < 4; j++) acc[i][j] = 0.f;
    float sqA = 0.f, sqB = 0.f;

    for (int kc = 0; kc < KPER / 32; kc++) {
        int k0 = kbase + kc * 32;
        int f4 = (k0 >> 2) + kq;
        // inline maxpool over 20 regions (raw mem read, 128B per (row,region))
        float4 a4 = make_float4(-FLT_MAX, -FLT_MAX, -FLT_MAX, -FLT_MAX);
        float4 b4 = a4;
#pragma unroll 5
        for (int o = 0; o < OBJn; o++) {
            a4 = fmax4(a4, __ldg(pA4 + (size_t)o * (Dn / 4) + f4));
            b4 = fmax4(b4, __ldg(pB4 + (size_t)o * (Dn / 4) + f4));
        }
        if (!vA) a4 = make_float4(0.f, 0.f, 0.f, 0.f);
        if (!vB) b4 = make_float4(0.f, 0.f, 0.f, 0.f);
        sqA += a4.x * a4.x + a4.y * a4.y + a4.z * a4.z + a4.w * a4.w;
        sqB += b4.x * b4.x + b4.y * b4.y + b4.z * b4.z + b4.w * b4.w;

        __syncthreads();   // previous iter's Bs/As reads done
        Bs[lm][kq * 4 + 0] = a4.x; Bs[lm][kq * 4 + 1] = a4.y;
        Bs[lm][kq * 4 + 2] = a4.z; Bs[lm][kq * 4 + 3] = a4.w;
        Bs[lm + 32][kq * 4 + 0] = b4.x; Bs[lm + 32][kq * 4 + 1] = b4.y;
        Bs[lm + 32][kq * 4 + 2] = b4.z; Bs[lm + 32][kq * 4 + 3] = b4.w;
#pragma unroll
        for (int idx = tid; idx < 80 * 32; idx += 256) {
            int r = idx >> 5, kk = idx & 31;
            As[r][kk] = g_rmaxn[(size_t)r * Dn + k0 + kk];
        }
        __syncthreads();
#pragma unroll
        for (int kk = 0; kk < 32; kk++) {
            float a[5], b[4];
#pragma unroll
            for (int i = 0; i < 5; i++) a[i] = As[ty * 5 + i][kk];
#pragma unroll
            for (int j = 0; j < 4; j++) b[j] = Bs[tx * 4 + j][kk];
#pragma unroll
            for (int i = 0; i < 5; i++)
#pragma unroll
                for (int j = 0; j < 4; j++) acc[i][j] = fmaf(a[i], b[j], acc[i][j]);
        }
    }

    // write raw-dot partials
    float* dst = g_partial + (size_t)ks * BFn * MPAD;
#pragma unroll
    for (int i = 0; i < 5; i++)
#pragma unroll
        for (int j = 0; j < 4; j++)
            dst[(ty * 5 + i) * MPAD + m0 + tx * 4 + j] = acc[i][j];

    // reduce sumsq across the 8 kq lanes of each row (consecutive lanes)
#pragma unroll
    for (int o = 4; o; o >>= 1) {
        sqA += __shfl_down_sync(0xffffffffu, sqA, o, 8);
        sqB += __shfl_down_sync(0xffffffffu, sqB, o, 8);
    }
    if (kq == 0) {
        g_psq[ks * MPAD + m0 + lm]      = sqA;
        g_psq[ks * MPAD + m0 + lm + 32] = sqB;
    }
}

// ---------------- K3b: reduce k-split partials, normalize, argmax per mem half -------
__global__ __launch_bounds__(256) void k_argmax() {
    int r = blockIdx.x;
    int tid = threadIdx.x;
    float bv[2] = {-FLT_MAX, -FLT_MAX};
    int   bm[2] = {0, 0};
    for (int m = tid; m < 2 * Mn; m += 256) {
        float s = 0.f, n = 0.f;
#pragma unroll
        for (int ks = 0; ks < KSPLIT; ks++) {
            s += g_partial[(size_t)ks * BFn * MPAD + (size_t)r * MPAD + m];
            n += g_psq[ks * MPAD + m];
        }
        float inv = 1.f / fmaxf(sqrtf(n), 1e-12f);
        float sc = s * inv;
        int h = (m >= Mn);
        int mm = h ? m - Mn : m;
        if (sc > bv[h] || (sc == bv[h] && mm < bm[h])) { bv[h] = sc; bm[h] = mm; }
    }
    __shared__ float sv[2][256];
    __shared__ int   sm[2][256];
    sv[0][tid] = bv[0]; sm[0][tid] = bm[0];
    sv[1][tid] = bv[1]; sm[1][tid] = bm[1];
    __syncthreads();
    for (int st = 128; st; st >>= 1) {
        if (tid < st) {
#pragma unroll
            for (int h = 0; h < 2; h++) {
                float ov = sv[h][tid + st]; int om = sm[h][tid + st];
                if (ov > sv[h][tid] || (ov == sv[h][tid] && om < sm[h][tid])) {
                    sv[h][tid] = ov; sm[h][tid] = om;
                }
            }
        }
        __syncthreads();
    }
    if (tid == 0) { g_sim[r] = sm[0][0]; g_sim[BFn + r] = sm[1][0]; }
}

// ---------------- K4: frame selection (high/low idx), gather row ids, write sims ------
__global__ void k_idx(const float* __restrict__ qr, const int* __restrict__ rnd,
                      float* __restrict__ out, long long out_size, long long rpn2) {
    int t = threadIdx.x;
    if (t >= 16) return;
    int b = t >> 2, q = t & 3;                // t = b*4 + q
    const float* w = qr + (b * Qn + q) * Fn;
    int hi = 0; float hv = w[0];
    for (int f = 1; f < Fn; f++) if (w[f] > hv) { hv = w[f]; hi = f; }
    int rr = rnd[b * Qn + q];
    int lo = 0;
    for (int i = 0; i < Fn; i++) {
        int rank = 0;
        for (int j = 0; j < Fn; j++)
            rank += (w[j] < w[i]) || (w[j] == w[i] && j < i);
        if (rank == rr) { lo = i; break; }
    }
    g_high[t] = hi; g_low[t] = lo;
    g_rowP[t] = g_sim[b * Fn + lo];           // mem1 row for Rp replacement
    g_rowN[t] = g_sim[BFn + b * Fn + lo];     // mem2 row for Rn replacement (at LOW idx!)
    if (out_size >= rpn2 + 32) {
        out[(size_t)rpn2 + (q * Bn + b)]      = (float)g_sim[BFn + b * Fn + hi]; // high_sim
        out[(size_t)rpn2 + 16 + (q * Bn + b)] = (float)g_sim[b * Fn + lo];       // low_sim
    }
}

// ---------------- K5a: bulk fill — read input once per (b,f), fan out to 8 rows -------
__global__ __launch_bounds__(256) void k_fill(const float* __restrict__ inp,
                                              float* __restrict__ out) {
    int bf = blockIdx.x;
    int b = bf / Fn, f = bf % Fn;
    int lows[4], highs[4];
#pragma unroll
    for (int q = 0; q < 4; q++) { lows[q] = g_low[b * 4 + q]; highs[q] = g_high[b * 4 + q]; }
    const float4* src = (const float4*)(inp + (size_t)bf * ROWn);
    float4* o4 = (float4*)out;
    const float* invp = g_invnorm + bf * OBJn;
    const size_t rpn4 = RPN / 4;
    int e4base = blockIdx.y * 1280;
#pragma unroll
    for (int i = 0; i < 5; i++) {
        int e4 = e4base + threadIdx.x + i * 256;
        int oo = e4 >> 10;                     // region index (4096 floats = 1024 float4)
        float inv = invp[oo];
        float4 v = src[e4];
        v.x *= inv; v.y *= inv; v.z *= inv; v.w *= inv;
#pragma unroll
        for (int q = 0; q < 4; q++) {
            size_t ob = ((size_t)((q * Bn + b) * Fn + f)) * (ROWn / 4) + e4;
            if (f != lows[q])  o4[ob] = v;          // Rp: R copy unless replaced
            if (f != highs[q]) o4[rpn4 + ob] = v;   // Rn: R copy unless replaced
        }
    }
}

// ---------------- K5b: replaced rows — gather raw mem rows into outputs ---------------
__global__ __launch_bounds__(256) void k_replace(const float* __restrict__ mem1,
                                                 const float* __restrict__ mem2,
                                                 float* __restrict__ out) {
    int t = blockIdx.x;
    int which = t & 1;         // 0: Rp/low/mem1   1: Rn/high/mem2
    int bq = t >> 1;           // b*4 + q
    int b = bq >> 2, q = bq & 3;
    int f, row;
    const float* src;
    if (which == 0) { f = g_low[bq];  row = g_rowP[bq]; src = mem1; }
    else            { f = g_high[bq]; row = g_rowN[bq]; src = mem2; }
    const float4* s4 = (const float4*)(src + (size_t)row * ROWn);
    float4* d4 = (float4*)(out + (size_t)which * RPN +
                           ((size_t)((q * Bn + b) * Fn + f)) * ROWn);
    int base = blockIdx.y * 2560;
#pragma unroll
    for (int i = 0; i < 10; i++) {
        int e4 = base + threadIdx.x + i * 256;
        d4[e4] = s4[e4];
    }
}

// ---------------- launch ----------------
extern "C" void kernel_launch(void* const* d_in, const int* in_sizes, int n_in,
                              void* d_out, int out_size) {
    const float* qr   = (const float*)d_in[0];   // [4,4,20]
    const float* inp  = (const float*)d_in[1];   // [4,20,20,4096]
    const float* mem1 = (const float*)d_in[2];   // [1000,81920]
    const float* mem2 = (const float*)d_in[3];   // [1000,81920]
    const int*   rnd  = (const int*)d_in[4];     // [4,4,1]
    float* out = (float*)d_out;

    k_rstats<<<BFn, 256>>>(inp);
    k_gemm_fused<<<dim3(32, KSPLIT), 256>>>(mem1, mem2);
    k_argmax<<<BFn, 256>>>();
    k_idx<<<1, 32>>>(qr, rnd, out, (long long)out_size, (long long)(2 * RPN));
    k_fill<<<dim3(BFn, 16), 256>>>(inp, out);
    k_replace<<<dim3(32, 8), 256>>>(mem1, mem2, out);
}

// round 3
// speedup vs baseline: 1.4222x; 1.4222x over previous
#include <cuda_runtime.h>
#include <float.h>
#include <math.h>

// Problem constants
#define Bn   4
#define Qn   4
#define Fn   20
#define OBJn 20
#define Dn   4096
#define Mn   1000
#define ROWn (OBJn * Dn)          // 81920 floats per (frame|mem) row
#define BFn  (Bn * Fn)            // 80
#define KSPLIT 8
#define MPAD 2048

static const size_t RPN = (size_t)Qn * Bn * Fn * ROWn;   // 26,214,400 elems per big output

// ---------------- device scratch (static allocation; no cudaMalloc allowed) ----------
__device__ float g_mem_mp[2 * Mn * Dn];          // 32.8 MB: normalized maxpooled mem1|mem2
__device__ float g_rmaxn[BFn * Dn];              // 1.3 MB: normalized maxpooled R rows
__device__ float g_invnorm[BFn * OBJn];          // per-region inverse norms
__device__ float g_partial[KSPLIT * BFn * MPAD]; // 5.2 MB: GEMM k-split partial sums
__device__ int   g_sim[2 * BFn];                 // sim1 (0..79), sim2 (80..159)
__device__ int   g_high[16], g_low[16];          // indexed by b*4+q

// ---------------- helpers ----------------
__device__ __forceinline__ float block_reduce_sum(float v) {
    __shared__ float sh[32];
    __shared__ float res;
    int lane = threadIdx.x & 31, w = threadIdx.x >> 5;
#pragma unroll
    for (int o = 16; o; o >>= 1) v += __shfl_down_sync(0xffffffffu, v, o);
    __syncthreads();                 // protect sh/res reuse across calls
    if (!lane) sh[w] = v;
    __syncthreads();
    if (w == 0) {
        float x = (lane < (int)(blockDim.x >> 5)) ? sh[lane] : 0.f;
#pragma unroll
        for (int o = 16; o; o >>= 1) x += __shfl_down_sync(0xffffffffu, x, o);
        if (!lane) res = x;
    }
    __syncthreads();
    return res;
}

__device__ __forceinline__ float4 fmax4(float4 a, float4 b) {
    a.x = fmaxf(a.x, b.x); a.y = fmaxf(a.y, b.y);
    a.z = fmaxf(a.z, b.z); a.w = fmaxf(a.w, b.w);
    return a;
}

// ---------------- K_sel: frame selection from qr/rnd only (no argmax dependency) -----
__global__ void k_sel(const float* __restrict__ qr, const int* __restrict__ rnd) {
    int t = threadIdx.x;
    if (t >= 16) return;
    int b = t >> 2, q = t & 3;                // t = b*4 + q
    const float* w = qr + (b * Qn + q) * Fn;
    int hi = 0; float hv = w[0];
    for (int f = 1; f < Fn; f++) if (w[f] > hv) { hv = w[f]; hi = f; }
    int rr = rnd[b * Qn + q];
    int lo = 0;
    for (int i = 0; i < Fn; i++) {
        int rank = 0;
        for (int j = 0; j < Fn; j++)
            rank += (w[j] < w[i]) || (w[j] == w[i] && j < i);
        if (rank == rr) { lo = i; break; }
    }
    g_high[t] = hi; g_low[t] = lo;
}

// ---------------- K1: mem max-pool + l2norm -> g_mem_mp (pure streaming) -------------
__global__ __launch_bounds__(256) void k_mem_mp(const float* __restrict__ mem1,
                                                const float* __restrict__ mem2) {
    int row = blockIdx.x;
    const float* src = (row >= Mn) ? (mem2 + (size_t)(row - Mn) * ROWn)
                                   : (mem1 + (size_t)row * ROWn);
    float4 mx[4];
#pragma unroll
    for (int i = 0; i < 4; i++) mx[i] = make_float4(-FLT_MAX, -FLT_MAX, -FLT_MAX, -FLT_MAX);
    for (int o = 0; o < OBJn; o++) {
        const float4* p = (const float4*)(src + (size_t)o * Dn);
#pragma unroll
        for (int i = 0; i < 4; i++) mx[i] = fmax4(mx[i], p[threadIdx.x + i * 256]);
    }
    float s = 0.f;
#pragma unroll
    for (int i = 0; i < 4; i++)
        s += mx[i].x * mx[i].x + mx[i].y * mx[i].y + mx[i].z * mx[i].z + mx[i].w * mx[i].w;
    s = block_reduce_sum(s);
    float inv = 1.f / fmaxf(sqrtf(s), 1e-12f);
    float4* out = (float4*)(g_mem_mp + (size_t)row * Dn);
#pragma unroll
    for (int i = 0; i < 4; i++) {
        float4 v = mx[i];
        v.x *= inv; v.y *= inv; v.z *= inv; v.w *= inv;
        out[threadIdx.x + i * 256] = v;
    }
}

// ---------------- K2: per-(b,f) region norms + maxpool + l2norm -> g_rmaxn, g_invnorm --
__global__ __launch_bounds__(256) void k_rstats(const float* __restrict__ inp) {
    int bf = blockIdx.x;
    const float* base = inp + (size_t)bf * ROWn;
    float4 mx[4];
#pragma unroll
    for (int i = 0; i < 4; i++) mx[i] = make_float4(-FLT_MAX, -FLT_MAX, -FLT_MAX, -FLT_MAX);
    for (int o = 0; o < OBJn; o++) {
        float4 x[4];
        const float4* p = (const float4*)(base + (size_t)o * Dn);
        float s = 0.f;
#pragma unroll
        for (int i = 0; i < 4; i++) {
            x[i] = p[threadIdx.x + i * 256];
            s += x[i].x * x[i].x + x[i].y * x[i].y + x[i].z * x[i].z + x[i].w * x[i].w;
        }
        s = block_reduce_sum(s);
        float inv = 1.f / fmaxf(sqrtf(s), 1e-12f);
        if (threadIdx.x == 0) g_invnorm[bf * OBJn + o] = inv;
#pragma unroll
        for (int i = 0; i < 4; i++) {
            float4 v = x[i];
            v.x *= inv; v.y *= inv; v.z *= inv; v.w *= inv;
            mx[i] = fmax4(mx[i], v);
        }
    }
    float s2 = 0.f;
#pragma unroll
    for (int i = 0; i < 4; i++)
        s2 += mx[i].x * mx[i].x + mx[i].y * mx[i].y + mx[i].z * mx[i].z + mx[i].w * mx[i].w;
    s2 = block_reduce_sum(s2);
    float inv2 = 1.f / fmaxf(sqrtf(s2), 1e-12f);
    float4* out = (float4*)(g_rmaxn + (size_t)bf * Dn);
#pragma unroll
    for (int i = 0; i < 4; i++) {
        float4 v = mx[i];
        v.x *= inv2; v.y *= inv2; v.z *= inv2; v.w *= inv2;
        out[threadIdx.x + i * 256] = v;
    }
}

// ---------------- K3: scores = Rmaxn[80,4096] @ mem_mp^T[4096,2000], k-split partials --
__global__ __launch_bounds__(256) void k_gemm() {
    __shared__ float As[80][33];
    __shared__ float Bs[64][33];
    int tid = threadIdx.x;
    int tx = tid & 15, ty = tid >> 4;     // tx: m (16x4=64), ty: r (16x5=80)
    int m0 = blockIdx.x * 64;
    int kbase = blockIdx.y * 512;
    float acc[5][4];
#pragma unroll
    for (int i = 0; i < 5; i++)
#pragma unroll
        for (int j = 0; j < 4; j++) acc[i][j] = 0.f;

    for (int kc = 0; kc < 16; kc++) {
        int k0 = kbase + kc * 32;
        __syncthreads();
#pragma unroll
        for (int idx = tid; idx < 80 * 32; idx += 256) {
            int r = idx >> 5, kk = idx & 31;
            As[r][kk] = g_rmaxn[(size_t)r * Dn + k0 + kk];
        }
#pragma unroll
        for (int idx = tid; idx < 64 * 32; idx += 256) {
            int m = idx >> 5, kk = idx & 31;
            int mg = m0 + m;
            Bs[m][kk] = (mg < 2 * Mn) ? g_mem_mp[(size_t)mg * Dn + k0 + kk] : 0.f;
        }
        __syncthreads();
#pragma unroll
        for (int kk = 0; kk < 32; kk++) {
            float a[5], b[4];
#pragma unroll
            for (int i = 0; i < 5; i++) a[i] = As[ty * 5 + i][kk];
#pragma unroll
            for (int j = 0; j < 4; j++) b[j] = Bs[tx * 4 + j][kk];
#pragma unroll
            for (int i = 0; i < 5; i++)
#pragma unroll
                for (int j = 0; j < 4; j++) acc[i][j] = fmaf(a[i], b[j], acc[i][j]);
        }
    }
    float* dst = g_partial + (size_t)blockIdx.y * BFn * MPAD;
#pragma unroll
    for (int i = 0; i < 5; i++)
#pragma unroll
        for (int j = 0; j < 4; j++)
            dst[(ty * 5 + i) * MPAD + m0 + tx * 4 + j] = acc[i][j];
}

// ---------------- K3b: reduce k-split partials + per-row argmax over each mem half ----
__global__ __launch_bounds__(256) void k_argmax() {
    int r = blockIdx.x;
    int tid = threadIdx.x;
    float bv[2] = {-FLT_MAX, -FLT_MAX};
    int   bm[2] = {0, 0};
    for (int m = tid; m < 2 * Mn; m += 256) {
        float s = 0.f;
#pragma unroll
        for (int ks = 0; ks < KSPLIT; ks++)
            s += g_partial[(size_t)ks * BFn * MPAD + (size_t)r * MPAD + m];
        int h = (m >= Mn);
        int mm = h ? m - Mn : m;
        if (s > bv[h] || (s == bv[h] && mm < bm[h])) { bv[h] = s; bm[h] = mm; }
    }
    __shared__ float sv[2][256];
    __shared__ int   sm[2][256];
    sv[0][tid] = bv[0]; sm[0][tid] = bm[0];
    sv[1][tid] = bv[1]; sm[1][tid] = bm[1];
    __syncthreads();
    for (int st = 128; st; st >>= 1) {
        if (tid < st) {
#pragma unroll
            for (int h = 0; h < 2; h++) {
                float ov = sv[h][tid + st]; int om = sm[h][tid + st];
                if (ov > sv[h][tid] || (ov == sv[h][tid] && om < sm[h][tid])) {
                    sv[h][tid] = ov; sm[h][tid] = om;
                }
            }
        }
        __syncthreads();
    }
    if (tid == 0) { g_sim[r] = sm[0][0]; g_sim[BFn + r] = sm[1][0]; }
}

// ---------------- K5a: bulk fill — read input once per (b,f), fan out to 8 rows -------
// grid (80, 16) x 256 threads; chunk = 5120 elems = 1280 float4
__global__ __launch_bounds__(256) void k_fill(const float* __restrict__ inp,
                                              float* __restrict__ out) {
    int bf = blockIdx.x;
    int b = bf / Fn, f = bf % Fn;
    int lows[4], highs[4];
#pragma unroll
    for (int q = 0; q < 4; q++) { lows[q] = g_low[b * 4 + q]; highs[q] = g_high[b * 4 + q]; }
    const float4* src = (const float4*)(inp + (size_t)bf * ROWn);
    float4* o4 = (float4*)out;
    const float* invp = g_invnorm + bf * OBJn;
    const size_t rpn4 = RPN / 4;
    int e4base = blockIdx.y * 1280;
#pragma unroll
    for (int i = 0; i < 5; i++) {
        int e4 = e4base + threadIdx.x + i * 256;
        int oo = e4 >> 10;                     // region index (4096 floats = 1024 float4)
        float inv = invp[oo];
        float4 v = src[e4];
        v.x *= inv; v.y *= inv; v.z *= inv; v.w *= inv;
#pragma unroll
        for (int q = 0; q < 4; q++) {
            size_t ob = ((size_t)((q * Bn + b) * Fn + f)) * (ROWn / 4) + e4;
            if (f != lows[q])  o4[ob] = v;          // Rp: R copy unless replaced
            if (f != highs[q]) o4[rpn4 + ob] = v;   // Rn: R copy unless replaced
        }
    }
}

// ---------------- K5b: replaced rows + sim outputs (reads g_sim directly) -------------
// grid (33, 8) x 256; x<32: copy mem rows; x==32 (y==0): write high_sim/low_sim.
__global__ __launch_bounds__(256) void k_replace(const float* __restrict__ mem1,
                                                 const float* __restrict__ mem2,
                                                 float* __restrict__ out,
                                                 long long out_size) {
    int t = blockIdx.x;
    if (t == 32) {
        if (blockIdx.y == 0 && threadIdx.x < 16) {
            int bq = threadIdx.x;               // b*4 + q
            int b = bq >> 2, q = bq & 3;
            long long rpn2 = (long long)(2 * RPN);
            if (out_size >= rpn2 + 32) {
                out[(size_t)rpn2 + (q * Bn + b)]      =
                    (float)g_sim[BFn + b * Fn + g_high[bq]];   // high_sim
                out[(size_t)rpn2 + 16 + (q * Bn + b)] =
                    (float)g_sim[b * Fn + g_low[bq]];          // low_sim
            }
        }
        return;
    }
    int which = t & 1;         // 0: Rp/low/mem1   1: Rn/high/mem2
    int bq = t >> 1;           // b*4 + q
    int b = bq >> 2, q = bq & 3;
    int f, row;
    const float* src;
    int lo = g_low[bq];
    if (which == 0) { f = lo;         row = g_sim[b * Fn + lo];       src = mem1; }
    else            { f = g_high[bq]; row = g_sim[BFn + b * Fn + lo]; src = mem2; }
    const float4* s4 = (const float4*)(src + (size_t)row * ROWn);
    float4* d4 = (float4*)(out + (size_t)which * RPN +
                           ((size_t)((q * Bn + b) * Fn + f)) * ROWn);
    int base = blockIdx.y * 2560;
#pragma unroll
    for (int i = 0; i < 10; i++) {
        int e4 = base + threadIdx.x + i * 256;
        d4[e4] = s4[e4];
    }
}

// ---------------- stream/event setup (once, outside capture: first call is uncaptured) -
static cudaStream_t make_side_stream() {
    cudaStream_t s = 0;
    if (cudaStreamCreateWithFlags(&s, cudaStreamNonBlocking) != cudaSuccess) s = 0;
    return s;
}
static cudaEvent_t make_event() {
    cudaEvent_t e = 0;
    if (cudaEventCreateWithFlags(&e, cudaEventDisableTiming) != cudaSuccess) e = 0;
    return e;
}

// ---------------- launch ----------------
extern "C" void kernel_launch(void* const* d_in, const int* in_sizes, int n_in,
                              void* d_out, int out_size) {
    const float* qr   = (const float*)d_in[0];   // [4,4,20]
    const float* inp  = (const float*)d_in[1];   // [4,20,20,4096]
    const float* mem1 = (const float*)d_in[2];   // [1000,81920]
    const float* mem2 = (const float*)d_in[3];   // [1000,81920]
    const int*   rnd  = (const int*)d_in[4];     // [4,4,1]
    float* out = (float*)d_out;

    static cudaStream_t s1  = make_side_stream();
    static cudaEvent_t  ev0 = make_event();
    static cudaEvent_t  ev1 = make_event();

    if (s1 && ev0 && ev1) {
        // fork side chain: sel -> rstats -> fill  (independent of mem chain)
        cudaEventRecord(ev0, 0);
        cudaStreamWaitEvent(s1, ev0, 0);
        k_sel<<<1, 32, 0, s1>>>(qr, rnd);
        k_rstats<<<BFn, 256, 0, s1>>>(inp);
        k_fill<<<dim3(BFn, 16), 256, 0, s1>>>(inp, out);
        cudaEventRecord(ev1, s1);
        // main chain: mem_mp -> gemm -> argmax
        k_mem_mp<<<2 * Mn, 256>>>(mem1, mem2);
        k_gemm<<<dim3(32, KSPLIT), 256>>>();
        k_argmax<<<BFn, 256>>>();
        // join, then replacements (need g_sim + g_high/g_low)
        cudaStreamWaitEvent(0, ev1, 0);
        k_replace<<<dim3(33, 8), 256>>>(mem1, mem2, out, (long long)out_size);
    } else {
        // serial fallback
        k_sel<<<1, 32>>>(qr, rnd);
        k_rstats<<<BFn, 256>>>(inp);
        k_mem_mp<<<2 * Mn, 256>>>(mem1, mem2);
        k_gemm<<<dim3(32, KSPLIT), 256>>>();
        k_argmax<<<BFn, 256>>>();
        k_fill<<<dim3(BFn, 16), 256>>>(inp, out);
        k_replace<<<dim3(33, 8), 256>>>(mem1, mem2, out, (long long)out_size);
    }
}